// round 1
// baseline (speedup 1.0000x reference)
#include <cuda_runtime.h>

#define NB   24
#define ND   256
#define NP1  25
#define INFX 1e9f

// One CTA per batch. 128 threads (4 warps).
//  - cur slots tile staged in smem (raw values, needed for gather output)
//  - cost[i][j] = 1 - <prev_i/|prev_i|, cur_j/|cur_j|>, stored [24][25] padded
//  - warp 0 runs warp-parallel Jonker-Volgenant (lane j owns column j)
//  - cooperative gather copy: out[i][:] = cur[col[i]][:]
__global__ __launch_bounds__(128) void hung_kernel(
    const float* __restrict__ slots,
    const float* __restrict__ prev,
    float* __restrict__ out)
{
    __shared__ float cur_s[NB * ND];       // 24 KB raw current slots
    __shared__ float cost_s[NB * NP1];     // padded cost matrix
    __shared__ float u_sh[NB];             // row potentials
    __shared__ float inv_pn_sh[NB];
    __shared__ float inv_cn_sh[NB];
    __shared__ int   col_sh[NB];           // col_sh[row] = matched column

    const int b    = blockIdx.x;
    const int tid  = threadIdx.x;
    const int lane = tid & 31;
    const int warp = tid >> 5;

    const float* sb = slots + (size_t)b * NB * ND;
    const float* pb = prev  + (size_t)b * NB * ND;
    float*       ob = out   + (size_t)b * NB * ND;

    // ---- stage current slots tile into smem (float4, coalesced) ----
    {
        const float4* sb4 = (const float4*)sb;
        float4* cur4 = (float4*)cur_s;
        #pragma unroll
        for (int idx = tid; idx < NB * ND / 4; idx += 128)
            cur4[idx] = sb4[idx];
    }
    __syncthreads();

    // ---- norms: warp per row (6 rows per warp) ----
    for (int i = warp; i < NB; i += 4) {
        // lane l covers bytes [l*16, l*16+16) and [512 + l*16, ...): conflict-free LDS,
        // perfectly coalesced LDG.
        float4 c0 = *(const float4*)(cur_s + i * ND + lane * 4);
        float4 c1 = *(const float4*)(cur_s + i * ND + 128 + lane * 4);
        float4 q0 = *(const float4*)(pb + i * ND + lane * 4);
        float4 q1 = *(const float4*)(pb + i * ND + 128 + lane * 4);
        float sc = c0.x*c0.x + c0.y*c0.y + c0.z*c0.z + c0.w*c0.w
                 + c1.x*c1.x + c1.y*c1.y + c1.z*c1.z + c1.w*c1.w;
        float sp = q0.x*q0.x + q0.y*q0.y + q0.z*q0.z + q0.w*q0.w
                 + q1.x*q1.x + q1.y*q1.y + q1.z*q1.z + q1.w*q1.w;
        #pragma unroll
        for (int off = 16; off; off >>= 1) {
            sc += __shfl_xor_sync(0xffffffffu, sc, off);
            sp += __shfl_xor_sync(0xffffffffu, sp, off);
        }
        if (lane == 0) {
            inv_cn_sh[i] = 1.0f / fmaxf(sqrtf(sc), 1e-12f);
            inv_pn_sh[i] = 1.0f / fmaxf(sqrtf(sp), 1e-12f);
        }
    }
    __syncthreads();

    // ---- cost matrix: warp per row i, prev row hoisted into registers ----
    for (int i = warp; i < NB; i += 4) {
        float4 p0 = *(const float4*)(pb + i * ND + lane * 4);
        float4 p1 = *(const float4*)(pb + i * ND + 128 + lane * 4);
        float spn = inv_pn_sh[i];
        for (int j = 0; j < NB; j++) {
            float4 c0 = *(const float4*)(cur_s + j * ND + lane * 4);
            float4 c1 = *(const float4*)(cur_s + j * ND + 128 + lane * 4);
            float acc = p0.x * c0.x;
            acc = fmaf(p0.y, c0.y, acc);
            acc = fmaf(p0.z, c0.z, acc);
            acc = fmaf(p0.w, c0.w, acc);
            acc = fmaf(p1.x, c1.x, acc);
            acc = fmaf(p1.y, c1.y, acc);
            acc = fmaf(p1.z, c1.z, acc);
            acc = fmaf(p1.w, c1.w, acc);
            #pragma unroll
            for (int off = 16; off; off >>= 1)
                acc += __shfl_xor_sync(0xffffffffu, acc, off);
            if (lane == 0)
                cost_s[i * NP1 + j] = 1.0f - acc * spn * inv_cn_sh[j];
        }
    }
    __syncthreads();

    // ---- Hungarian (e-maxx JV), warp 0 only, lane j owns column j ----
    // lanes 0..23 = real columns, lane 24 = virtual start column, lanes 25..31 inert
    if (warp == 0) {
        if (lane < NB) u_sh[lane] = 0.0f;
        __syncwarp();

        float v = 0.0f;   // column potential (lane-owned)
        int   p = -1;     // row assigned to this column (-1 = free)

        for (int i = 0; i < NB; i++) {
            if (lane == NB) p = i;      // p[n] = i
            float minv = INFX;
            int   way  = 0;
            bool  used = (lane > NB);   // lanes 25..31 permanently inert
            int   j0   = NB;
            int   pj0  = i;             // p[j0] at loop entry

            while (true) {
                if (lane == j0) used = true;
                float u_i0 = u_sh[pj0];
                const float* crow = cost_s + pj0 * NP1;
                if (lane < NB && !used) {
                    float cv = crow[lane] - u_i0 - v;   // reduced cost
                    if (cv < minv) { minv = cv; way = j0; }
                }
                // warp argmin over unused real columns, first-index tie-break
                float bv = (lane < NB && !used) ? minv : INFX;
                int   bj = lane;
                #pragma unroll
                for (int off = 16; off; off >>= 1) {
                    float ov = __shfl_xor_sync(0xffffffffu, bv, off);
                    int   oj = __shfl_xor_sync(0xffffffffu, bj, off);
                    if (ov < bv || (ov == bv && oj < bj)) { bv = ov; bj = oj; }
                }
                float delta = bv;
                // dual update (same order as reference)
                if (used && lane <= NB) {
                    v -= delta;
                    u_sh[p] += delta;    // distinct rows per used col: race-free
                } else if (lane < NB) {
                    minv -= delta;
                }
                __syncwarp();            // make u_sh updates visible next step
                j0  = bj;
                pj0 = __shfl_sync(0xffffffffu, p, j0);
                if (pj0 < 0) break;      // reached a free column
            }

            // augment back along parent pointers to virtual column
            while (j0 != NB) {
                int jp = __shfl_sync(0xffffffffu, way, j0);
                int pv = __shfl_sync(0xffffffffu, p, jp);
                if (lane == j0) p = pv;
                j0 = jp;
            }
        }
        if (lane < NB) col_sh[p] = lane;   // col index of row p[j] is j
    }
    __syncthreads();

    // ---- gather output: out[row][:] = cur[col[row]][:] ----
    {
        float4* ob4 = (float4*)ob;
        const float4* cur4 = (const float4*)cur_s;
        #pragma unroll
        for (int idx = tid; idx < NB * ND / 4; idx += 128) {
            int row = idx >> 6;          // 64 float4 per row
            int c   = idx & 63;
            int src = col_sh[row];
            ob4[idx] = cur4[src * 64 + c];
        }
    }
}

extern "C" void kernel_launch(void* const* d_in, const int* in_sizes, int n_in,
                              void* d_out, int out_size) {
    const float* slots = (const float*)d_in[0];
    const float* prev  = (const float*)d_in[1];
    float* out = (float*)d_out;
    int B = in_sizes[0] / (NB * ND);
    hung_kernel<<<B, 128>>>(slots, prev, out);
}

// round 2
// speedup vs baseline: 1.5345x; 1.5345x over previous
#include <cuda_runtime.h>
#include <cstdint>

#define NB   24
#define NP1  25
#define ND   256
#define INFX 1e9f
#define FULL 0xffffffffu

// packed fp32x2 FMA (sm_100+ PTX; doubles used as 64-bit carriers for f32 pairs)
__device__ __forceinline__ double ffma2(double a, double b, double c) {
    double r;
    asm("fma.rn.f32x2 %0, %1, %2, %3;" : "=d"(r) : "d"(a), "d"(b), "d"(c));
    return r;
}
__device__ __forceinline__ float pairsum(double a) {
    return __int_as_float(__double2loint(a)) + __int_as_float(__double2hiint(a));
}
// order-preserving float<->uint for unsigned min-reduction
__device__ __forceinline__ unsigned fenc(float x) {
    unsigned b = __float_as_uint(x);
    return b ^ (((unsigned)((int)b >> 31)) | 0x80000000u);
}
__device__ __forceinline__ float fdec(unsigned k) {
    unsigned m = ((unsigned)((int)(~k) >> 31)) | 0x80000000u;
    return __uint_as_float(k ^ m);
}

// One warp handles one batch end-to-end. CTA = 4 warps = 4 batches. No __syncthreads.
__global__ __launch_bounds__(128) void hung_kernel(
    const float* __restrict__ slots,
    const float* __restrict__ prev,
    float* __restrict__ out,
    int B)
{
    __shared__ float cost_s[4][NB * NP1];
    __shared__ float ipn_s[4][NB];
    __shared__ float icn_s[4][NB];
    __shared__ int   col_s[4][NB];

    const int lane = threadIdx.x & 31;
    const int w    = threadIdx.x >> 5;
    const int b    = blockIdx.x * 4 + w;
    if (b >= B) return;   // whole-warp uniform exit; no block syncs exist

    const float* sb = slots + (size_t)b * NB * ND;
    const float* pb = prev  + (size_t)b * NB * ND;
    float*       ob = out   + (size_t)b * NB * ND;

    // ---------------- norms: warp-cooperative per row, dual folded reduce ----------------
    for (int i = 0; i < NB; i++) {
        const double2* pr = (const double2*)(pb + i * ND + lane * 8);
        const double2* cr = (const double2*)(sb + i * ND + lane * 8);
        double2 pa = pr[0], pb2 = pr[1];
        double2 ca = cr[0], cb2 = cr[1];
        double ap = 0.0, ac = 0.0;
        ap = ffma2(pa.x, pa.x, ap);  ap = ffma2(pa.y, pa.y, ap);
        ap = ffma2(pb2.x, pb2.x, ap); ap = ffma2(pb2.y, pb2.y, ap);
        ac = ffma2(ca.x, ca.x, ac);  ac = ffma2(ca.y, ca.y, ac);
        ac = ffma2(cb2.x, cb2.x, ac); ac = ffma2(cb2.y, cb2.y, ac);
        float sp = pairsum(ap), sc = pairsum(ac);
        sp += __shfl_xor_sync(FULL, sp, 16);
        sc += __shfl_xor_sync(FULL, sc, 16);
        float z = (lane & 16) ? sc : sp;
        z += __shfl_xor_sync(FULL, z, 8);
        z += __shfl_xor_sync(FULL, z, 4);
        z += __shfl_xor_sync(FULL, z, 2);
        z += __shfl_xor_sync(FULL, z, 1);
        if (lane == 0)  ipn_s[w][i] = 1.0f / fmaxf(sqrtf(z), 1e-12f);
        if (lane == 16) icn_s[w][i] = 1.0f / fmaxf(sqrtf(z), 1e-12f);
    }
    __syncwarp();

    // ---------------- cost matrix: i-block 4, f32x2 FMA, folded 4-dot reduce ----------------
    for (int ib = 0; ib < 6; ib++) {
        const int i0 = ib * 4;
        const double2* r0 = (const double2*)(pb + (i0 + 0) * ND + lane * 8);
        const double2* r1 = (const double2*)(pb + (i0 + 1) * ND + lane * 8);
        const double2* r2 = (const double2*)(pb + (i0 + 2) * ND + lane * 8);
        const double2* r3 = (const double2*)(pb + (i0 + 3) * ND + lane * 8);
        double2 p0a = r0[0], p0b = r0[1];
        double2 p1a = r1[0], p1b = r1[1];
        double2 p2a = r2[0], p2b = r2[1];
        double2 p3a = r3[0], p3b = r3[1];

        for (int j = 0; j < NB; j++) {
            const double2* cp = (const double2*)(sb + j * ND + lane * 8);
            double2 c0 = cp[0], c1 = cp[1];
            double a0 = 0.0, a1 = 0.0, a2 = 0.0, a3 = 0.0;
            a0 = ffma2(p0a.x, c0.x, a0); a0 = ffma2(p0a.y, c0.y, a0);
            a0 = ffma2(p0b.x, c1.x, a0); a0 = ffma2(p0b.y, c1.y, a0);
            a1 = ffma2(p1a.x, c0.x, a1); a1 = ffma2(p1a.y, c0.y, a1);
            a1 = ffma2(p1b.x, c1.x, a1); a1 = ffma2(p1b.y, c1.y, a1);
            a2 = ffma2(p2a.x, c0.x, a2); a2 = ffma2(p2a.y, c0.y, a2);
            a2 = ffma2(p2b.x, c1.x, a2); a2 = ffma2(p2b.y, c1.y, a2);
            a3 = ffma2(p3a.x, c0.x, a3); a3 = ffma2(p3a.y, c0.y, a3);
            a3 = ffma2(p3b.x, c1.x, a3); a3 = ffma2(p3b.y, c1.y, a3);
            float s0 = pairsum(a0), s1 = pairsum(a1);
            float s2 = pairsum(a2), s3 = pairsum(a3);
            // folded 4-stream reduction: 9 shfls for 4 dots
            s0 += __shfl_xor_sync(FULL, s0, 16);
            s1 += __shfl_xor_sync(FULL, s1, 16);
            s2 += __shfl_xor_sync(FULL, s2, 16);
            s3 += __shfl_xor_sync(FULL, s3, 16);
            float z1 = (lane & 16) ? s1 : s0;
            float z2 = (lane & 16) ? s3 : s2;
            z1 += __shfl_xor_sync(FULL, z1, 8);
            z2 += __shfl_xor_sync(FULL, z2, 8);
            float zz = (lane & 8) ? z2 : z1;
            zz += __shfl_xor_sync(FULL, zz, 4);
            zz += __shfl_xor_sync(FULL, zz, 2);
            zz += __shfl_xor_sync(FULL, zz, 1);
            // lane0->dot0, lane8->dot2, lane16->dot1, lane24->dot3
            if ((lane & 7) == 0) {
                int which  = lane >> 3;
                int dotidx = ((which & 1) << 1) | (which >> 1);
                int row    = i0 + dotidx;
                cost_s[w][row * NP1 + j] = 1.0f - zz * ipn_s[w][row] * icn_s[w][j];
            }
        }
    }
    __syncwarp();

    // ---------------- JV Hungarian: lane j owns column j; u,v in lane registers ----------------
    // Exact e-maxx arithmetic: u[i0]/v[j] read during a search equal their row-start
    // values (their columns only become used in the same step that reads them), so the
    // per-step dual updates are lane-local (+= delta under used/row_used flags).
    {
        const float* cw = cost_s[w];
        const unsigned ENC_INF = fenc(INFX);
        float u = 0.0f, v = 0.0f;
        int p = -1;

        for (int i = 0; i < NB; i++) {
            if (lane == NB) p = i;        // virtual start column holds new row
            float minv = INFX;
            int   way  = 0;
            bool  used = false;
            bool  row_used = false;
            int   j0  = NB;
            int   pj0 = i;

            while (true) {
                used     = used     || (lane == j0);
                row_used = row_used || (lane == pj0);
                float u_i0 = __shfl_sync(FULL, u, pj0);
                float crow = (lane < NB) ? cw[pj0 * NP1 + lane] : 0.0f;
                bool  act  = (lane < NB) && !used;
                if (act) {
                    float cv = crow - u_i0 - v;       // reduced cost (row-start duals)
                    if (cv < minv) { minv = cv; way = j0; }
                }
                unsigned key  = act ? fenc(minv) : ENC_INF;
                unsigned kmin = __reduce_min_sync(FULL, key);
                int j1 = __ffs(__ballot_sync(FULL, key == kmin)) - 1;  // first-index tie-break
                float delta = fdec(kmin);
                if (used)     v    -= delta;
                if (row_used) u    += delta;
                if (act)      minv -= delta;
                j0  = j1;
                pj0 = __shfl_sync(FULL, p, j0);
                if (pj0 < 0) break;      // reached a free column
            }
            // augment along parent pointers back to virtual column
            while (j0 != NB) {
                int jp = __shfl_sync(FULL, way, j0);
                int pv = __shfl_sync(FULL, p, jp);
                if (lane == j0) p = pv;
                j0 = jp;
            }
        }
        if (lane < NB) col_s[w][p] = lane;   // col index of row p[j] is j
    }
    __syncwarp();

    // ---------------- gather: out[row][:] = slots[col[row]][:] ----------------
    for (int rr = 0; rr < NB; rr++) {
        int src = col_s[w][rr];
        const float4* s4 = (const float4*)(sb + src * ND);
        float4*       o4 = (float4*)(ob + rr * ND);
        o4[lane]      = s4[lane];
        o4[lane + 32] = s4[lane + 32];
    }
}

extern "C" void kernel_launch(void* const* d_in, const int* in_sizes, int n_in,
                              void* d_out, int out_size) {
    const float* slots = (const float*)d_in[0];
    const float* prev  = (const float*)d_in[1];
    float* out = (float*)d_out;
    int B = in_sizes[0] / (NB * ND);
    int grid = (B + 3) / 4;
    hung_kernel<<<grid, 128>>>(slots, prev, out, B);
}

// round 3
// speedup vs baseline: 1.5898x; 1.0361x over previous
#include <cuda_runtime.h>
#include <cstdint>

#define NB    24
#define NP1   25
#define NCOST (NB * NP1)      // 600 floats per batch
#define ND    256
#define INFX  1e9f
#define FULL  0xffffffffu
#define MAXB  2048

// cost scratch: [B][24][25] fp32 (~4.9 MB), static device array (no allocs)
__device__ float g_cost[(size_t)MAXB * NCOST];

// packed fp32x2 FMA (sm_100+); doubles are 64-bit carriers for f32 pairs
__device__ __forceinline__ double ffma2(double a, double b, double c) {
    double r;
    asm("fma.rn.f32x2 %0, %1, %2, %3;" : "=d"(r) : "d"(a), "d"(b), "d"(c));
    return r;
}
__device__ __forceinline__ float pairsum(double a) {
    return __int_as_float(__double2loint(a)) + __int_as_float(__double2hiint(a));
}
// order-preserving float<->uint for unsigned min-reduction
__device__ __forceinline__ unsigned fenc(float x) {
    unsigned b = __float_as_uint(x);
    return b ^ (((unsigned)((int)b >> 31)) | 0x80000000u);
}
__device__ __forceinline__ float fdec(unsigned k) {
    unsigned m = ((unsigned)((int)(~k) >> 31)) | 0x80000000u;
    return __uint_as_float(k ^ m);
}

// ============================================================================
// Kernel 1: cost matrices. One warp per (batch, 4-row block): 6*B warps total.
// Warp keeps its 4 prev rows in registers; per cur row j it computes 4 dot
// products + cur_j . cur_j via a 5-stream folded shuffle reduction, then the 4
// writer lanes {0,8,16,24} emit cost entries.
// Fold result lane map: lane0->s0, lane16->s1, lane8->s2, lane24->s3,
// (lane&4)->s4.  row_local = 2*bit3(lane) + bit4(lane).
// ============================================================================
__global__ __launch_bounds__(256) void costk(
    const float* __restrict__ slots,
    const float* __restrict__ prev,
    int B)
{
    const int lane = threadIdx.x & 31;
    const int gw   = (blockIdx.x * 256 + threadIdx.x) >> 5;
    const int b    = gw / 6;
    const int ib   = gw % 6;
    if (b >= B) return;

    const float* pb = prev  + (size_t)b * NB * ND;
    const float* sb = slots + (size_t)b * NB * ND;
    const int i0 = ib * 4;

    // ---- 4 prev rows into registers (8 floats per lane per row) ----
    double2 p0a, p0b, p1a, p1b, p2a, p2b, p3a, p3b;
    {
        const double2* r0 = (const double2*)(pb + (i0 + 0) * ND + lane * 8);
        const double2* r1 = (const double2*)(pb + (i0 + 1) * ND + lane * 8);
        const double2* r2 = (const double2*)(pb + (i0 + 2) * ND + lane * 8);
        const double2* r3 = (const double2*)(pb + (i0 + 3) * ND + lane * 8);
        p0a = r0[0]; p0b = r0[1];
        p1a = r1[0]; p1b = r1[1];
        p2a = r2[0]; p2b = r2[1];
        p3a = r3[0]; p3b = r3[1];
    }

    // ---- prev-row inverse norms (4-stream folded reduce) ----
    float ipn;   // valid at lanes 0,8,16,24 for rows i0+{0,2,1,3}
    {
        double a0 = 0.0, a1 = 0.0, a2 = 0.0, a3 = 0.0;
        a0 = ffma2(p0a.x, p0a.x, a0); a0 = ffma2(p0a.y, p0a.y, a0);
        a0 = ffma2(p0b.x, p0b.x, a0); a0 = ffma2(p0b.y, p0b.y, a0);
        a1 = ffma2(p1a.x, p1a.x, a1); a1 = ffma2(p1a.y, p1a.y, a1);
        a1 = ffma2(p1b.x, p1b.x, a1); a1 = ffma2(p1b.y, p1b.y, a1);
        a2 = ffma2(p2a.x, p2a.x, a2); a2 = ffma2(p2a.y, p2a.y, a2);
        a2 = ffma2(p2b.x, p2b.x, a2); a2 = ffma2(p2b.y, p2b.y, a2);
        a3 = ffma2(p3a.x, p3a.x, a3); a3 = ffma2(p3a.y, p3a.y, a3);
        a3 = ffma2(p3b.x, p3b.x, a3); a3 = ffma2(p3b.y, p3b.y, a3);
        float s0 = pairsum(a0), s1 = pairsum(a1);
        float s2 = pairsum(a2), s3 = pairsum(a3);
        s0 += __shfl_xor_sync(FULL, s0, 16);
        s1 += __shfl_xor_sync(FULL, s1, 16);
        s2 += __shfl_xor_sync(FULL, s2, 16);
        s3 += __shfl_xor_sync(FULL, s3, 16);
        float t0 = (lane & 16) ? s1 : s0;
        float t1 = (lane & 16) ? s3 : s2;
        t0 += __shfl_xor_sync(FULL, t0, 8);
        t1 += __shfl_xor_sync(FULL, t1, 8);
        float u = (lane & 8) ? t1 : t0;
        u += __shfl_xor_sync(FULL, u, 4);
        u += __shfl_xor_sync(FULL, u, 2);
        u += __shfl_xor_sync(FULL, u, 1);
        ipn = 1.0f / fmaxf(sqrtf(u), 1e-12f);
    }

    float* gc = g_cost + (size_t)b * NCOST;
    const bool writer   = ((lane & 7) == 0);
    const int  row_loc  = (((lane >> 3) & 1) << 1) | ((lane >> 4) & 1);
    const int  row      = i0 + row_loc;

    // ---- per cur row j: 4 dots + cur norm; 5-stream folded reduce ----
    for (int j = 0; j < NB; j++) {
        const double2* cp = (const double2*)(sb + j * ND + lane * 8);
        double2 c0 = cp[0], c1 = cp[1];
        double a0 = 0.0, a1 = 0.0, a2 = 0.0, a3 = 0.0, a4 = 0.0;
        a0 = ffma2(p0a.x, c0.x, a0); a0 = ffma2(p0a.y, c0.y, a0);
        a0 = ffma2(p0b.x, c1.x, a0); a0 = ffma2(p0b.y, c1.y, a0);
        a1 = ffma2(p1a.x, c0.x, a1); a1 = ffma2(p1a.y, c0.y, a1);
        a1 = ffma2(p1b.x, c1.x, a1); a1 = ffma2(p1b.y, c1.y, a1);
        a2 = ffma2(p2a.x, c0.x, a2); a2 = ffma2(p2a.y, c0.y, a2);
        a2 = ffma2(p2b.x, c1.x, a2); a2 = ffma2(p2b.y, c1.y, a2);
        a3 = ffma2(p3a.x, c0.x, a3); a3 = ffma2(p3a.y, c0.y, a3);
        a3 = ffma2(p3b.x, c1.x, a3); a3 = ffma2(p3b.y, c1.y, a3);
        a4 = ffma2(c0.x, c0.x, a4);  a4 = ffma2(c0.y, c0.y, a4);
        a4 = ffma2(c1.x, c1.x, a4);  a4 = ffma2(c1.y, c1.y, a4);
        float s0 = pairsum(a0), s1 = pairsum(a1);
        float s2 = pairsum(a2), s3 = pairsum(a3), s4 = pairsum(a4);
        s0 += __shfl_xor_sync(FULL, s0, 16);
        s1 += __shfl_xor_sync(FULL, s1, 16);
        s2 += __shfl_xor_sync(FULL, s2, 16);
        s3 += __shfl_xor_sync(FULL, s3, 16);
        s4 += __shfl_xor_sync(FULL, s4, 16);
        float t0 = (lane & 16) ? s1 : s0;
        float t1 = (lane & 16) ? s3 : s2;
        float t2 = s4;
        t0 += __shfl_xor_sync(FULL, t0, 8);
        t1 += __shfl_xor_sync(FULL, t1, 8);
        t2 += __shfl_xor_sync(FULL, t2, 8);
        float u0 = (lane & 8) ? t1 : t0;
        float u1 = t2;
        u0 += __shfl_xor_sync(FULL, u0, 4);
        u1 += __shfl_xor_sync(FULL, u1, 4);
        float wv = (lane & 4) ? u1 : u0;
        wv += __shfl_xor_sync(FULL, wv, 2);
        wv += __shfl_xor_sync(FULL, wv, 1);
        // broadcast cur-norm sum (held by all bit4=1 lanes) to writer lanes
        float cn = __shfl_sync(FULL, wv, lane | 4);
        if (writer) {
            float icn = 1.0f / fmaxf(sqrtf(cn), 1e-12f);
            gc[row * NP1 + j] = 1.0f - wv * ipn * icn;
        }
    }
}

// ============================================================================
// Kernel 2: JV Hungarian + gather. One warp per batch, 4 warps/CTA, no
// __syncthreads. Cost staged global -> smem per warp. JV identical to the
// validated R2 formulation (e-maxx arithmetic, lane-register duals,
// redux.min + ballot first-index argmin).
// ============================================================================
__global__ __launch_bounds__(128) void jvk(
    const float* __restrict__ slots,
    float* __restrict__ out,
    int B)
{
    __shared__ float cost_s[4][NCOST];
    __shared__ int   col_s[4][NB];

    const int lane = threadIdx.x & 31;
    const int w    = threadIdx.x >> 5;
    const int b    = blockIdx.x * 4 + w;
    if (b >= B) return;

    // ---- stage this batch's cost matrix into smem (600 floats) ----
    {
        const float4* gc4 = (const float4*)(g_cost + (size_t)b * NCOST);
        float4* cs4 = (float4*)cost_s[w];
        #pragma unroll
        for (int t = lane; t < NCOST / 4; t += 32)
            cs4[t] = gc4[t];
    }
    __syncwarp();

    // ---- JV Hungarian: lane j owns column j; u,v in lane registers ----
    {
        const float* cw = cost_s[w];
        const unsigned ENC_INF = fenc(INFX);
        float u = 0.0f, v = 0.0f;
        int p = -1;

        for (int i = 0; i < NB; i++) {
            if (lane == NB) p = i;        // virtual start column holds new row
            float minv = INFX;
            int   way  = 0;
            bool  used = false;
            bool  row_used = false;
            int   j0  = NB;
            int   pj0 = i;

            while (true) {
                used     = used     || (lane == j0);
                row_used = row_used || (lane == pj0);
                float u_i0 = __shfl_sync(FULL, u, pj0);
                float crow = (lane < NB) ? cw[pj0 * NP1 + lane] : 0.0f;
                bool  act  = (lane < NB) && !used;
                if (act) {
                    float cv = crow - u_i0 - v;       // reduced cost
                    if (cv < minv) { minv = cv; way = j0; }
                }
                unsigned key  = act ? fenc(minv) : ENC_INF;
                unsigned kmin = __reduce_min_sync(FULL, key);
                int j1 = __ffs(__ballot_sync(FULL, key == kmin)) - 1;
                float delta = fdec(kmin);
                if (used)     v    -= delta;
                if (row_used) u    += delta;
                if (act)      minv -= delta;
                j0  = j1;
                pj0 = __shfl_sync(FULL, p, j0);
                if (pj0 < 0) break;      // reached a free column
            }
            // augment along parent pointers back to virtual column
            while (j0 != NB) {
                int jp = __shfl_sync(FULL, way, j0);
                int pv = __shfl_sync(FULL, p, jp);
                if (lane == j0) p = pv;
                j0 = jp;
            }
        }
        if (lane < NB) col_s[w][p] = lane;   // col index of row p[j] is j
    }
    __syncwarp();

    // ---- gather: out[row][:] = slots[col[row]][:] ----
    const float* sb = slots + (size_t)b * NB * ND;
    float*       ob = out   + (size_t)b * NB * ND;
    for (int rr = 0; rr < NB; rr++) {
        int src = col_s[w][rr];
        const float4* s4 = (const float4*)(sb + src * ND);
        float4*       o4 = (float4*)(ob + rr * ND);
        o4[lane]      = s4[lane];
        o4[lane + 32] = s4[lane + 32];
    }
}

extern "C" void kernel_launch(void* const* d_in, const int* in_sizes, int n_in,
                              void* d_out, int out_size) {
    const float* slots = (const float*)d_in[0];
    const float* prev  = (const float*)d_in[1];
    float* out = (float*)d_out;
    int B = in_sizes[0] / (NB * ND);
    if (B > MAXB) B = MAXB;

    int warps1 = B * 6;
    int grid1  = (warps1 * 32 + 255) / 256;
    costk<<<grid1, 256>>>(slots, prev, B);

    int grid2 = (B + 3) / 4;
    jvk<<<grid2, 128>>>(slots, out, B);
}

// round 4
// speedup vs baseline: 1.8333x; 1.1531x over previous
#include <cuda_runtime.h>
#include <cstdint>

#define NB    24
#define NP1   25
#define NCOST (NB * NP1)      // 600 floats per batch
#define ND    256
#define INFX  1e9f
#define FULL  0xffffffffu
#define MAXB  2048

// cost scratch: [B][24][25] fp32 (~4.9 MB), static device array (no allocs)
__device__ float g_cost[(size_t)MAXB * NCOST];

// packed fp32x2 FMA (sm_100+); doubles are 64-bit carriers for f32 pairs
__device__ __forceinline__ double ffma2(double a, double b, double c) {
    double r;
    asm("fma.rn.f32x2 %0, %1, %2, %3;" : "=d"(r) : "d"(a), "d"(b), "d"(c));
    return r;
}
__device__ __forceinline__ float pairsum(double a) {
    return __int_as_float(__double2loint(a)) + __int_as_float(__double2hiint(a));
}
// order-preserving float<->uint for unsigned min-reduction
__device__ __forceinline__ unsigned fenc(float x) {
    unsigned b = __float_as_uint(x);
    return b ^ (((unsigned)((int)b >> 31)) | 0x80000000u);
}
__device__ __forceinline__ float fdec(unsigned k) {
    unsigned m = ((unsigned)((int)(~k) >> 31)) | 0x80000000u;
    return __uint_as_float(k ^ m);
}

// canonical lane holding stream m after fold8: bit0->lane bit4, bit1->bit3, bit2->bit2
__device__ __forceinline__ int lane_of(int m) {
    return ((m & 1) << 4) | ((m & 2) << 2) | (m & 4);
}

// 8-stream folded warp reduction. Returns: lane L holds full sum of stream
// m(L) = bit4(L) | bit3(L)<<1 | bit2(L)<<2   (duplicated across lanes sharing
// those bits). 15 shfls, log-depth, 8-wide ILP at the top level.
__device__ __forceinline__ float fold8(
    float q0, float q1, float q2, float q3,
    float q4, float q5, float q6, float q7, int lane)
{
    q0 += __shfl_xor_sync(FULL, q0, 16);
    q1 += __shfl_xor_sync(FULL, q1, 16);
    q2 += __shfl_xor_sync(FULL, q2, 16);
    q3 += __shfl_xor_sync(FULL, q3, 16);
    q4 += __shfl_xor_sync(FULL, q4, 16);
    q5 += __shfl_xor_sync(FULL, q5, 16);
    q6 += __shfl_xor_sync(FULL, q6, 16);
    q7 += __shfl_xor_sync(FULL, q7, 16);
    float t0 = (lane & 16) ? q1 : q0;
    float t1 = (lane & 16) ? q3 : q2;
    float t2 = (lane & 16) ? q5 : q4;
    float t3 = (lane & 16) ? q7 : q6;
    t0 += __shfl_xor_sync(FULL, t0, 8);
    t1 += __shfl_xor_sync(FULL, t1, 8);
    t2 += __shfl_xor_sync(FULL, t2, 8);
    t3 += __shfl_xor_sync(FULL, t3, 8);
    float u0 = (lane & 8) ? t1 : t0;
    float u1 = (lane & 8) ? t3 : t2;
    u0 += __shfl_xor_sync(FULL, u0, 4);
    u1 += __shfl_xor_sync(FULL, u1, 4);
    float v = (lane & 4) ? u1 : u0;
    v += __shfl_xor_sync(FULL, v, 2);
    v += __shfl_xor_sync(FULL, v, 1);
    return v;
}

// ============================================================================
// Kernel 1 (cost): warp = (batch, 4x4 tile of the 24x24 cost matrix).
// Lane owns k-slice {lane*4..+4} U {128+lane*4..+4} (two coalesced 16B chunks).
// Straight line: 16 LDG.128 -> 96 ffma2 (16 dots + 8 norms) -> 3x fold8 ->
// 2 predicated STG. CTA = 9 warps = one (batch, 12x12 quadrant) for L1 reuse.
// ============================================================================
__global__ __launch_bounds__(288) void costk(
    const float* __restrict__ slots,
    const float* __restrict__ prev,
    int B)
{
    const int lane = threadIdx.x & 31;
    const int wid  = threadIdx.x >> 5;     // 0..8
    const int b    = blockIdx.x >> 2;
    const int q    = blockIdx.x & 3;
    if (b >= B) return;
    const int qi = q >> 1, qj = q & 1;
    const int ti = qi * 3 + wid / 3;       // 0..5
    const int tj = qj * 3 + wid % 3;       // 0..5
    const int i0 = ti * 4, j0 = tj * 4;

    const float* pb = prev  + (size_t)b * (NB * ND) + i0 * ND;
    const float* sb = slots + (size_t)b * (NB * ND) + j0 * ND;

    // ---- coalesced loads: 4 prev rows + 4 cur rows, 8 floats per lane ----
    double2 P[4][2], C[4][2];
    #pragma unroll
    for (int r = 0; r < 4; r++) {
        const double2* pr = (const double2*)(pb + r * ND);
        const double2* cr = (const double2*)(sb + r * ND);
        P[r][0] = pr[lane];      P[r][1] = pr[lane + 32];
        C[r][0] = cr[lane];      C[r][1] = cr[lane + 32];
    }

    // ---- 16 dot partials + 8 norm partials (independent ffma2 chains) ----
    float s[16], np[4], nc[4];
    #pragma unroll
    for (int a = 0; a < 4; a++) {
        #pragma unroll
        for (int c = 0; c < 4; c++) {
            double acc = 0.0;
            acc = ffma2(P[a][0].x, C[c][0].x, acc);
            acc = ffma2(P[a][0].y, C[c][0].y, acc);
            acc = ffma2(P[a][1].x, C[c][1].x, acc);
            acc = ffma2(P[a][1].y, C[c][1].y, acc);
            s[a * 4 + c] = pairsum(acc);
        }
        double an = 0.0, cn = 0.0;
        an = ffma2(P[a][0].x, P[a][0].x, an);
        an = ffma2(P[a][0].y, P[a][0].y, an);
        an = ffma2(P[a][1].x, P[a][1].x, an);
        an = ffma2(P[a][1].y, P[a][1].y, an);
        cn = ffma2(C[a][0].x, C[a][0].x, cn);
        cn = ffma2(C[a][0].y, C[a][0].y, cn);
        cn = ffma2(C[a][1].x, C[a][1].x, cn);
        cn = ffma2(C[a][1].y, C[a][1].y, cn);
        np[a] = pairsum(an);
        nc[a] = pairsum(cn);
    }

    // ---- three 8-stream folds ----
    float v1 = fold8(s[0], s[1], s[2], s[3], s[4], s[5], s[6], s[7], lane);   // rows a=0,1
    float v2 = fold8(s[8], s[9], s[10], s[11], s[12], s[13], s[14], s[15], lane); // rows a=2,3
    float v3 = fold8(np[0], np[1], np[2], np[3], nc[0], nc[1], nc[2], nc[3], lane);

    float inv = 1.0f / fmaxf(sqrtf(v3), 1e-12f);

    // lane's stream index and writer fan-out
    const int m = ((lane >> 4) & 1) | (((lane >> 3) & 1) << 1) | (((lane >> 2) & 1) << 2);
    const int a  = m >> 2;        // 0..1
    const int c  = m & 3;         // 0..3
    float ipn1 = __shfl_sync(FULL, inv, lane_of(a));        // np[a]
    float ipn2 = __shfl_sync(FULL, inv, lane_of(2 + a));    // np[a+2]
    float icn  = __shfl_sync(FULL, inv, lane_of(4 + c));    // nc[c]

    if ((lane & 3) == 0) {
        float* gc = g_cost + (size_t)b * NCOST;
        gc[(i0 + a)     * NP1 + (j0 + c)] = 1.0f - v1 * ipn1 * icn;
        gc[(i0 + 2 + a) * NP1 + (j0 + c)] = 1.0f - v2 * ipn2 * icn;
    }
}

// ============================================================================
// Kernel 2: JV Hungarian + gather (unchanged, validated). One warp per batch,
// 4 warps/CTA, no __syncthreads.
// ============================================================================
__global__ __launch_bounds__(128) void jvk(
    const float* __restrict__ slots,
    float* __restrict__ out,
    int B)
{
    __shared__ float cost_s[4][NCOST];
    __shared__ int   col_s[4][NB];

    const int lane = threadIdx.x & 31;
    const int w    = threadIdx.x >> 5;
    const int b    = blockIdx.x * 4 + w;
    if (b >= B) return;

    // ---- stage this batch's cost matrix into smem (600 floats) ----
    {
        const float4* gc4 = (const float4*)(g_cost + (size_t)b * NCOST);
        float4* cs4 = (float4*)cost_s[w];
        #pragma unroll
        for (int t = lane; t < NCOST / 4; t += 32)
            cs4[t] = gc4[t];
    }
    __syncwarp();

    // ---- JV Hungarian: lane j owns column j; u,v in lane registers ----
    {
        const float* cw = cost_s[w];
        const unsigned ENC_INF = fenc(INFX);
        float u = 0.0f, v = 0.0f;
        int p = -1;

        for (int i = 0; i < NB; i++) {
            if (lane == NB) p = i;        // virtual start column holds new row
            float minv = INFX;
            int   way  = 0;
            bool  used = false;
            bool  row_used = false;
            int   j0  = NB;
            int   pj0 = i;

            while (true) {
                used     = used     || (lane == j0);
                row_used = row_used || (lane == pj0);
                float u_i0 = __shfl_sync(FULL, u, pj0);
                float crow = (lane < NB) ? cw[pj0 * NP1 + lane] : 0.0f;
                bool  act  = (lane < NB) && !used;
                if (act) {
                    float cv = crow - u_i0 - v;       // reduced cost
                    if (cv < minv) { minv = cv; way = j0; }
                }
                unsigned key  = act ? fenc(minv) : ENC_INF;
                unsigned kmin = __reduce_min_sync(FULL, key);
                int j1 = __ffs(__ballot_sync(FULL, key == kmin)) - 1;
                float delta = fdec(kmin);
                if (used)     v    -= delta;
                if (row_used) u    += delta;
                if (act)      minv -= delta;
                j0  = j1;
                pj0 = __shfl_sync(FULL, p, j0);
                if (pj0 < 0) break;      // reached a free column
            }
            // augment along parent pointers back to virtual column
            while (j0 != NB) {
                int jp = __shfl_sync(FULL, way, j0);
                int pv = __shfl_sync(FULL, p, jp);
                if (lane == j0) p = pv;
                j0 = jp;
            }
        }
        if (lane < NB) col_s[w][p] = lane;   // col index of row p[j] is j
    }
    __syncwarp();

    // ---- gather: out[row][:] = slots[col[row]][:] ----
    const float* sb = slots + (size_t)b * NB * ND;
    float*       ob = out   + (size_t)b * NB * ND;
    for (int rr = 0; rr < NB; rr++) {
        int src = col_s[w][rr];
        const float4* s4 = (const float4*)(sb + src * ND);
        float4*       o4 = (float4*)(ob + rr * ND);
        o4[lane]      = s4[lane];
        o4[lane + 32] = s4[lane + 32];
    }
}

extern "C" void kernel_launch(void* const* d_in, const int* in_sizes, int n_in,
                              void* d_out, int out_size) {
    const float* slots = (const float*)d_in[0];
    const float* prev  = (const float*)d_in[1];
    float* out = (float*)d_out;
    int B = in_sizes[0] / (NB * ND);
    if (B > MAXB) B = MAXB;

    costk<<<B * 4, 288>>>(slots, prev, B);

    int grid2 = (B + 3) / 4;
    jvk<<<grid2, 128>>>(slots, out, B);
}